// round 9
// baseline (speedup 1.0000x reference)
#include <cuda_runtime.h>
#include <cuda_bf16.h>
#include <math.h>
#include <stdint.h>

typedef unsigned long long ull;

// ---------------- f32x2 packed-math helpers ------------------------------------
__device__ __forceinline__ ull pack2(float lo, float hi) {
    ull r; asm("mov.b64 %0, {%1, %2};" : "=l"(r) : "f"(lo), "f"(hi)); return r;
}
__device__ __forceinline__ void unpack2(ull v, float& lo, float& hi) {
    asm("mov.b64 {%0, %1}, %2;" : "=f"(lo), "=f"(hi) : "l"(v));
}
__device__ __forceinline__ void fma2(ull& d, ull a, ull b) {
    asm("fma.rn.f32x2 %0, %1, %2, %0;" : "+l"(d) : "l"(a), "l"(b));
}

// ---------------- bf16 / mma helpers --------------------------------------------
__device__ __forceinline__ uint32_t packbf(float lo, float hi) {  // {lo->low16, hi->high16}
    uint32_t r; asm("cvt.rn.bf16x2.f32 %0, %1, %2;" : "=r"(r) : "f"(hi), "f"(lo)); return r;
}
__device__ __forceinline__ float loF(uint32_t u) { return __uint_as_float(u << 16); }
__device__ __forceinline__ float hiF(uint32_t u) { return __uint_as_float(u & 0xffff0000u); }
__device__ __forceinline__ float ex2f(float x) {
    float r; asm("ex2.approx.f32 %0, %1;" : "=f"(r) : "f"(x)); return r;
}

__device__ __forceinline__ uint32_t cvta_s(const void* p) {
    uint32_t a;
    asm("{ .reg .u64 t; cvta.to.shared.u64 t, %1; cvt.u32.u64 %0, t; }" : "=r"(a) : "l"(p));
    return a;
}
__device__ __forceinline__ void ldmx2(uint32_t& r0, uint32_t& r1, uint32_t a) {
    asm volatile("ldmatrix.sync.aligned.m8n8.x2.shared.b16 {%0,%1}, [%2];"
                 : "=r"(r0), "=r"(r1) : "r"(a));
}
__device__ __forceinline__ void ldmx4(uint32_t* r, uint32_t a) {
    asm volatile("ldmatrix.sync.aligned.m8n8.x4.shared.b16 {%0,%1,%2,%3}, [%4];"
                 : "=r"(r[0]), "=r"(r[1]), "=r"(r[2]), "=r"(r[3]) : "r"(a));
}
__device__ __forceinline__ void mma16816(float* c, const uint32_t* a, uint32_t b0, uint32_t b1) {
    asm volatile(
        "mma.sync.aligned.m16n8k16.row.col.f32.bf16.bf16.f32 "
        "{%0,%1,%2,%3}, {%4,%5,%6,%7}, {%8,%9}, {%0,%1,%2,%3};"
        : "+f"(c[0]), "+f"(c[1]), "+f"(c[2]), "+f"(c[3])
        : "r"(a[0]), "r"(a[1]), "r"(a[2]), "r"(a[3]), "r"(b0), "r"(b1));
}
__device__ __forceinline__ void cpa16(uint32_t dst, const void* src) {
    asm volatile("cp.async.cg.shared.global [%0], [%1], 16;" :: "r"(dst), "l"(src) : "memory");
}
#define CP_COMMIT() asm volatile("cp.async.commit_group;" ::: "memory")
#define CP_WAIT0()  asm volatile("cp.async.wait_group 0;" ::: "memory")

// ---------------- problem constants -------------------------------------------
#define BB 8
#define CC 64
#define HC 32
#define NN 4096
#define LOG2E 1.4426950408889634f

// ---------------- device scratch -----------------------------------------------
__device__ __align__(16) float g_xq[BB * CC * NN];            // [b][c][n]
__device__ __align__(16) unsigned short g_qhi[BB * NN * HC];  // bf16(q*log2e) hi
__device__ __align__(16) unsigned short g_qlo[BB * NN * HC];  // residual
__device__ __align__(16) unsigned short g_khi[BB * NN * HC];  // bf16 K
__device__ __align__(16) unsigned short g_vthi[BB * HC * NN]; // bf16 V^T [b][d][n]

// ---------------- kernel B: weight quant + x fake-quant + fused QKV -------------
__global__ void __launch_bounds__(128) k_xq_qkv(const float* __restrict__ x,
                                                const float* __restrict__ wq,
                                                const float* __restrict__ wk,
                                                const float* __restrict__ wv,
                                                const float* __restrict__ bq,
                                                const float* __restrict__ bk,
                                                const float* __restrict__ bv,
                                                const float* __restrict__ s_in_p) {
    extern __shared__ float smB[];
    float* xs = smB;                 // [64][128]
    float* ws = smB + CC * 128;      // [64][96]
    __shared__ float redw[12];
    const int t = threadIdx.x;
    const int b = blockIdx.y;
    const int n0 = blockIdx.x * 128;
    const float si = s_in_p[0];

    // ---- x fake-quant into smem + global ----
    const float* xb = x + ((size_t)b * CC) * NN + n0;
    float* xqb = g_xq + ((size_t)b * CC) * NN + n0;
#pragma unroll 4
    for (int c = 0; c < CC; c++) {
        float v = xb[c * NN + t];
        float r = rintf(v / si);
        r = fminf(fmaxf(r, -128.f), 127.f);
        float q = r * si;
        xqb[c * NN + t] = q;
        xs[c * 128 + t] = q;
    }

    // ---- per-tensor weight max-abs (redundant per block; deterministic) ----
    float mx0 = 0.f, mx1 = 0.f, mx2 = 0.f;
    for (int i = t; i < CC * HC; i += 128) {
        mx0 = fmaxf(mx0, fabsf(wq[i]));
        mx1 = fmaxf(mx1, fabsf(wk[i]));
        mx2 = fmaxf(mx2, fabsf(wv[i]));
    }
#pragma unroll
    for (int s = 16; s; s >>= 1) {
        mx0 = fmaxf(mx0, __shfl_xor_sync(0xffffffffu, mx0, s));
        mx1 = fmaxf(mx1, __shfl_xor_sync(0xffffffffu, mx1, s));
        mx2 = fmaxf(mx2, __shfl_xor_sync(0xffffffffu, mx2, s));
    }
    if ((t & 31) == 0) {
        redw[t >> 5] = mx0; redw[4 + (t >> 5)] = mx1; redw[8 + (t >> 5)] = mx2;
    }
    __syncthreads();
    float s0 = fmaxf(fmaxf(redw[0], redw[1]), fmaxf(redw[2], redw[3])) / 127.f;
    float s1 = fmaxf(fmaxf(redw[4], redw[5]), fmaxf(redw[6], redw[7])) / 127.f;
    float s2 = fmaxf(fmaxf(redw[8], redw[9]), fmaxf(redw[10], redw[11])) / 127.f;
    // quantize weights into transposed smem [c][96]
    for (int i = t; i < CC * HC; i += 128) {
        int hc = i >> 6, c = i & 63;
        ws[c * 96 + hc]      = fminf(fmaxf(rintf(wq[i] / s0), -127.f), 127.f) * s0;
        ws[c * 96 + 32 + hc] = fminf(fmaxf(rintf(wk[i] / s1), -127.f), 127.f) * s1;
        ws[c * 96 + 64 + hc] = fminf(fmaxf(rintf(wv[i] / s2), -127.f), 127.f) * s2;
    }
    __syncthreads();

    ull aq[16], ak[16], av[16];
#pragma unroll
    for (int h = 0; h < 16; h++) {
        aq[h] = pack2(bq[2 * h], bq[2 * h + 1]);
        ak[h] = pack2(bk[2 * h], bk[2 * h + 1]);
        av[h] = pack2(bv[2 * h], bv[2 * h + 1]);
    }
#pragma unroll 2
    for (int c = 0; c < CC; c++) {
        float xv = xs[c * 128 + t];
        ull xp = pack2(xv, xv);
        const ulonglong2* wr = (const ulonglong2*)(ws + c * 96);
#pragma unroll
        for (int j = 0; j < 8; j++) {
            ulonglong2 u = wr[j];
            fma2(aq[2 * j], xp, u.x);
            fma2(aq[2 * j + 1], xp, u.y);
        }
#pragma unroll
        for (int j = 0; j < 8; j++) {
            ulonglong2 u = wr[8 + j];
            fma2(ak[2 * j], xp, u.x);
            fma2(ak[2 * j + 1], xp, u.y);
        }
#pragma unroll
        for (int j = 0; j < 8; j++) {
            ulonglong2 u = wr[16 + j];
            fma2(av[2 * j], xp, u.x);
            fma2(av[2 * j + 1], xp, u.y);
        }
    }

    size_t bn = (size_t)b * NN + n0 + t;
    // Q: scale by log2(e), store bf16 hi + residual lo. K: single bf16.
    uint32_t qh[16], ql[16], kh[16];
#pragma unroll
    for (int j = 0; j < 16; j++) {
        float f0, f1;
        unpack2(aq[j], f0, f1);
        f0 *= LOG2E; f1 *= LOG2E;
        uint32_t u = packbf(f0, f1);
        qh[j] = u;
        ql[j] = packbf(f0 - loF(u), f1 - hiF(u));
        unpack2(ak[j], f0, f1);
        kh[j] = packbf(f0, f1);
    }
    uint4* qhp = (uint4*)(g_qhi + bn * HC);
    uint4* qlp = (uint4*)(g_qlo + bn * HC);
    uint4* khp = (uint4*)(g_khi + bn * HC);
#pragma unroll
    for (int c4 = 0; c4 < 4; c4++) {
        uint4 u;
        u.x = qh[4 * c4]; u.y = qh[4 * c4 + 1]; u.z = qh[4 * c4 + 2]; u.w = qh[4 * c4 + 3];
        qhp[c4] = u;
        u.x = ql[4 * c4]; u.y = ql[4 * c4 + 1]; u.z = ql[4 * c4 + 2]; u.w = ql[4 * c4 + 3];
        qlp[c4] = u;
        u.x = kh[4 * c4]; u.y = kh[4 * c4 + 1]; u.z = kh[4 * c4 + 2]; u.w = kh[4 * c4 + 3];
        khp[c4] = u;
    }
    // V transposed, single bf16
    unsigned short* vh = g_vthi + (size_t)b * HC * NN + n0 + t;
#pragma unroll
    for (int j = 0; j < 16; j++) {
        float f0, f1;
        unpack2(av[j], f0, f1);
        uint32_t u = packbf(f0, f1);
        vh[(size_t)(2 * j) * NN] = (unsigned short)(u & 0xffffu);
        vh[(size_t)(2 * j + 1) * NN] = (unsigned short)(u >> 16);
    }
}

// ---------------- kernel C: HMMA flash attention + fused proj ---------------------
// grid (16, 8) = (q-tile 256, batch), 256 threads / 8 warps, 32 q-rows per warp.
// Asymmetric hi/lo: S = (Qhi+Qlo)*Kbf16, O = (Phi+Plo)*Vbf16 -> 128 MMA/warp/kt.
// exp folded to single ex2 (Q pre-scaled by log2e). K/V double-buffered cp.async.
#define SM_QHI 0            // 256 rows x 80B
#define SM_QLO 20480
#define SM_K   40960        // + buf*5120 : K 64x80
#define SM_V   51200        // + buf*4608 : V 32x144
#define SM_WP  60416        // wp quantized 64x32 f32
#define SM_BP  68608        // bp 64 f32
#define ATTN_SMEM 68864
// epilogue zs (256x34 f32 = 34816B) reuses the Q region at offset 0

__global__ void __launch_bounds__(256, 1) k_attn(const float* __restrict__ wp,
                                                 const float* __restrict__ bp,
                                                 const float* __restrict__ s_in_p,
                                                 const float* __restrict__ s_out_p,
                                                 float* __restrict__ out) {
    extern __shared__ char sm[];
    __shared__ float redp[8];
    uint32_t sb = cvta_s(sm);
    const int t = threadIdx.x;
    const int w = t >> 5, lane = t & 31;
    const int b = blockIdx.y, qt = blockIdx.x;
    const int q0 = w * 32;

    const char* pkhi = (const char*)g_khi + (size_t)b * NN * 64;
    const char* pvhi = (const char*)g_vthi + (size_t)b * HC * (NN * 2);

    // staging: K 256 x 16B + V 256 x 16B = 512 cp.async, 256 threads x 2
    auto stageKV = [&](int kt) {
        uint32_t kb = sb + SM_K + (kt & 1) * 5120;
        uint32_t vb = sb + SM_V + (kt & 1) * 4608;
#pragma unroll
        for (int i = 0; i < 2; i++) {
            int idx = t + i * 256;
            if (idx < 256) {
                int row = idx >> 2, ch = idx & 3;
                cpa16(kb + row * 80 + ch * 16,
                      pkhi + (size_t)(kt * 64 + row) * 64 + ch * 16);
            } else {
                int rem = idx & 255;
                int d = rem >> 3, ch = rem & 7;
                cpa16(vb + d * 144 + ch * 16,
                      pvhi + (size_t)d * (NN * 2) + kt * 128 + ch * 16);
            }
        }
    };

    // ---- prologue: stage Q + KV(0); quantize wp while cp.async flies ----
    {
        const char* pqhi = (const char*)g_qhi + (size_t)b * NN * 64;
        const char* pqlo = (const char*)g_qlo + (size_t)b * NN * 64;
#pragma unroll
        for (int i = 0; i < 8; i++) {
            int idx = t + i * 256;
            int part = idx >> 10, rem = idx & 1023;
            int row = rem >> 2, ch = rem & 3;
            const char* src = (part ? pqlo : pqhi) + (size_t)(qt * 256 + row) * 64 + ch * 16;
            cpa16(sb + SM_QHI + part * 20480 + row * 80 + ch * 16, src);
        }
    }
    stageKV(0);
    CP_COMMIT();
    {
        float mxp = 0.f;
        for (int i = t; i < CC * HC; i += 256) mxp = fmaxf(mxp, fabsf(wp[i]));
#pragma unroll
        for (int s = 16; s; s >>= 1) mxp = fmaxf(mxp, __shfl_xor_sync(0xffffffffu, mxp, s));
        if (lane == 0) redp[w] = mxp;
        __syncthreads();
        float sp = fmaxf(fmaxf(fmaxf(redp[0], redp[1]), fmaxf(redp[2], redp[3])),
                         fmaxf(fmaxf(redp[4], redp[5]), fmaxf(redp[6], redp[7]))) / 127.f;
        float* wsp = (float*)(sm + SM_WP);
        for (int i = t; i < CC * HC; i += 256)
            wsp[i] = fminf(fmaxf(rintf(wp[i] / sp), -127.f), 127.f) * sp;
        if (t < CC) ((float*)(sm + SM_BP))[t] = bp[t];
    }
    CP_WAIT0();
    __syncthreads();

    // Q fragments (2 m-tiles x 2 k16 chunks, hi + lo)
    uint32_t qfh[2][2][4], qfl[2][2][4];
#pragma unroll
    for (int m = 0; m < 2; m++) {
        uint32_t qa = sb + SM_QHI +
            (uint32_t)((q0 + m * 16 + (lane & 7) + ((lane >> 3) & 1) * 8) * 80 +
                       ((lane >> 4) & 1) * 16);
        ldmx4(qfh[m][0], qa);
        ldmx4(qfh[m][1], qa + 32);
        ldmx4(qfl[m][0], qa + 20480);
        ldmx4(qfl[m][1], qa + 20480 + 32);
    }

    float O[2][4][4];
    float l_acc[2][2] = {{0.f, 0.f}, {0.f, 0.f}};
#pragma unroll
    for (int m = 0; m < 2; m++)
#pragma unroll
        for (int n = 0; n < 4; n++)
#pragma unroll
            for (int i = 0; i < 4; i++) O[m][n][i] = 0.f;

    // ---- main loop: 64 tiles of 64 keys ----
    for (int kt = 0; kt < 64; kt++) {
        uint32_t kb = sb + SM_K + (kt & 1) * 5120;
        uint32_t vb = sb + SM_V + (kt & 1) * 4608;
        if (kt < 63) { stageKV(kt + 1); CP_COMMIT(); }

        // S = (Qhi + Qlo) * K   (K single bf16)
        float S[2][8][4];
#pragma unroll
        for (int m = 0; m < 2; m++)
#pragma unroll
            for (int j = 0; j < 8; j++)
#pragma unroll
                for (int i = 0; i < 4; i++) S[m][j][i] = 0.f;

#pragma unroll
        for (int j = 0; j < 8; j++) {
            uint32_t ka = kb + (uint32_t)((j * 8 + (lane & 7)) * 80 + ((lane >> 3) & 1) * 16);
#pragma unroll
            for (int ks = 0; ks < 2; ks++) {
                uint32_t b0, b1;
                ldmx2(b0, b1, ka + ks * 32);
                mma16816(S[0][j], qfh[0][ks], b0, b1);
                mma16816(S[0][j], qfl[0][ks], b0, b1);
                mma16816(S[1][j], qfh[1][ks], b0, b1);
                mma16816(S[1][j], qfl[1][ks], b0, b1);
            }
        }

        // Interleaved ex2/pack/PV in 16-key chunks (S pre-scaled by log2e; no max sub)
#pragma unroll
        for (int kk = 0; kk < 4; kk++) {
            uint32_t phi[2][4], plo[2][4];
#pragma unroll
            for (int m = 0; m < 2; m++) {
                const int j0 = 2 * kk, j1 = 2 * kk + 1;
                float e0 = ex2f(S[m][j0][0]);
                float e1 = ex2f(S[m][j0][1]);
                float e2 = ex2f(S[m][j0][2]);
                float e3 = ex2f(S[m][j0][3]);
                float e4 = ex2f(S[m][j1][0]);
                float e5 = ex2f(S[m][j1][1]);
                float e6 = ex2f(S[m][j1][2]);
                float e7 = ex2f(S[m][j1][3]);
                l_acc[m][0] += (e0 + e1) + (e4 + e5);
                l_acc[m][1] += (e2 + e3) + (e6 + e7);
                uint32_t u;
                u = packbf(e0, e1); phi[m][0] = u;
                plo[m][0] = packbf(e0 - loF(u), e1 - hiF(u));
                u = packbf(e2, e3); phi[m][1] = u;
                plo[m][1] = packbf(e2 - loF(u), e3 - hiF(u));
                u = packbf(e4, e5); phi[m][2] = u;
                plo[m][2] = packbf(e4 - loF(u), e5 - hiF(u));
                u = packbf(e6, e7); phi[m][3] = u;
                plo[m][3] = packbf(e6 - loF(u), e7 - hiF(u));
            }
            uint32_t va = vb + (uint32_t)((lane & 7) * 144 + ((lane >> 3) & 1) * 16 + kk * 32);
#pragma unroll
            for (int n = 0; n < 4; n++) {
                uint32_t b0, b1;
                ldmx2(b0, b1, va + n * 1152);
                mma16816(O[0][n], phi[0], b0, b1);
                mma16816(O[0][n], plo[0], b0, b1);
                mma16816(O[1][n], phi[1], b0, b1);
                mma16816(O[1][n], plo[1], b0, b1);
            }
        }

        if (kt < 63) CP_WAIT0();
        __syncthreads();
    }

    // ---- epilogue 1: l-reduce, normalize, fake-quant z, stage to smem (Q region) --
    const float si = s_in_p[0];
    const float so = s_out_p[0];
    float* zs = (float*)(sm + SM_QHI);
#pragma unroll
    for (int m = 0; m < 2; m++)
#pragma unroll
        for (int h = 0; h < 2; h++) {
            float lv = l_acc[m][h];
            lv += __shfl_xor_sync(0xffffffffu, lv, 1);
            lv += __shfl_xor_sync(0xffffffffu, lv, 2);
            float inv = 1.0f / lv;
            int row = q0 + m * 16 + (lane >> 2) + h * 8;
#pragma unroll
            for (int n = 0; n < 4; n++) {
                float z0 = O[m][n][h * 2 + 0] * inv;
                float z1 = O[m][n][h * 2 + 1] * inv;
                float r0 = fminf(fmaxf(rintf(z0 / si), -128.f), 127.f) * si;
                float r1 = fminf(fmaxf(rintf(z1 / si), -128.f), 127.f) * si;
                float2 u; u.x = r0; u.y = r1;
                *(float2*)(zs + row * 34 + n * 8 + (lane & 3) * 2) = u;
            }
        }
    __syncthreads();

    // ---- epilogue 2: output projection + residual + out fq (thread = pixel) ----
    {
        ull zp[16];
#pragma unroll
        for (int j = 0; j < 16; j++)
            zp[j] = pack2(zs[t * 34 + 2 * j], zs[t * 34 + 2 * j + 1]);
        const float* wsp = (const float*)(sm + SM_WP);
        const float* bps = (const float*)(sm + SM_BP);
        const float* xqb = g_xq + ((size_t)b * CC) * NN + qt * 256 + t;
        float* ob = out + ((size_t)b * CC) * NN + qt * 256 + t;
#pragma unroll
        for (int c0 = 0; c0 < CC; c0 += 16) {
            float xv[16];
#pragma unroll
            for (int u = 0; u < 16; u++) xv[u] = xqb[(size_t)(c0 + u) * NN];
#pragma unroll
            for (int u = 0; u < 16; u++) {
                int c = c0 + u;
                ull a0 = 0ull, a1 = 0ull;
                const ulonglong2* wr = (const ulonglong2*)(wsp + c * HC);
#pragma unroll
                for (int j = 0; j < 8; j++) {
                    ulonglong2 uu = wr[j];
                    fma2(a0, zp[2 * j], uu.x);
                    fma2(a1, zp[2 * j + 1], uu.y);
                }
                float f0, f1, f2, f3;
                unpack2(a0, f0, f1);
                unpack2(a1, f2, f3);
                float val = xv[u] + (f0 + f1) + (f2 + f3) + bps[c];
                float r = rintf(val / so);
                r = fminf(fmaxf(r, -128.f), 127.f);
                ob[(size_t)c * NN] = r * so;
            }
        }
    }
}

// ---------------- launch ----------------------------------------------------------
extern "C" void kernel_launch(void* const* d_in, const int* in_sizes, int n_in,
                              void* d_out, int out_size) {
    const float* x     = (const float*)d_in[0];
    const float* wq    = (const float*)d_in[1];
    const float* bq    = (const float*)d_in[2];
    const float* wk    = (const float*)d_in[3];
    const float* bk    = (const float*)d_in[4];
    const float* wv    = (const float*)d_in[5];
    const float* bv    = (const float*)d_in[6];
    const float* wp    = (const float*)d_in[7];
    const float* bp    = (const float*)d_in[8];
    const float* s_in  = (const float*)d_in[9];
    const float* s_out = (const float*)d_in[10];
    float* out = (float*)d_out;

    const int smemB = (CC * 128 + CC * 96) * 4;
    cudaFuncSetAttribute(k_xq_qkv, cudaFuncAttributeMaxDynamicSharedMemorySize, smemB);
    cudaFuncSetAttribute(k_attn, cudaFuncAttributeMaxDynamicSharedMemorySize, ATTN_SMEM);

    k_xq_qkv<<<dim3(32, 8), 128, smemB>>>(x, wq, wk, wv, bq, bk, bv, s_in);
    k_attn<<<dim3(16, 8), 256, ATTN_SMEM>>>(wp, bp, s_in, s_out, out);
}

// round 10
// speedup vs baseline: 1.1876x; 1.1876x over previous
#include <cuda_runtime.h>
#include <cuda_bf16.h>
#include <math.h>
#include <stdint.h>

typedef unsigned long long ull;

// ---------------- f32x2 packed-math helpers ------------------------------------
__device__ __forceinline__ ull pack2(float lo, float hi) {
    ull r; asm("mov.b64 %0, {%1, %2};" : "=l"(r) : "f"(lo), "f"(hi)); return r;
}
__device__ __forceinline__ void unpack2(ull v, float& lo, float& hi) {
    asm("mov.b64 {%0, %1}, %2;" : "=f"(lo), "=f"(hi) : "l"(v));
}
__device__ __forceinline__ void fma2(ull& d, ull a, ull b) {
    asm("fma.rn.f32x2 %0, %1, %2, %0;" : "+l"(d) : "l"(a), "l"(b));
}

// ---------------- bf16 / mma helpers --------------------------------------------
__device__ __forceinline__ uint32_t packbf(float lo, float hi) {  // {lo->low16, hi->high16}
    uint32_t r; asm("cvt.rn.bf16x2.f32 %0, %1, %2;" : "=r"(r) : "f"(hi), "f"(lo)); return r;
}
__device__ __forceinline__ float loF(uint32_t u) { return __uint_as_float(u << 16); }
__device__ __forceinline__ float hiF(uint32_t u) { return __uint_as_float(u & 0xffff0000u); }
__device__ __forceinline__ float ex2f(float x) {
    float r; asm("ex2.approx.f32 %0, %1;" : "=f"(r) : "f"(x)); return r;
}

__device__ __forceinline__ uint32_t cvta_s(const void* p) {
    uint32_t a;
    asm("{ .reg .u64 t; cvta.to.shared.u64 t, %1; cvt.u32.u64 %0, t; }" : "=r"(a) : "l"(p));
    return a;
}
__device__ __forceinline__ void ldmx4(uint32_t* r, uint32_t a) {
    asm volatile("ldmatrix.sync.aligned.m8n8.x4.shared.b16 {%0,%1,%2,%3}, [%4];"
                 : "=r"(r[0]), "=r"(r[1]), "=r"(r[2]), "=r"(r[3]) : "r"(a));
}
__device__ __forceinline__ void mma16816(float* c, const uint32_t* a, uint32_t b0, uint32_t b1) {
    asm volatile(
        "mma.sync.aligned.m16n8k16.row.col.f32.bf16.bf16.f32 "
        "{%0,%1,%2,%3}, {%4,%5,%6,%7}, {%8,%9}, {%0,%1,%2,%3};"
        : "+f"(c[0]), "+f"(c[1]), "+f"(c[2]), "+f"(c[3])
        : "r"(a[0]), "r"(a[1]), "r"(a[2]), "r"(a[3]), "r"(b0), "r"(b1));
}
__device__ __forceinline__ void cpa16(uint32_t dst, const void* src) {
    asm volatile("cp.async.cg.shared.global [%0], [%1], 16;" :: "r"(dst), "l"(src) : "memory");
}
#define CP_COMMIT() asm volatile("cp.async.commit_group;" ::: "memory")
#define CP_WAIT0()  asm volatile("cp.async.wait_group 0;" ::: "memory")

// ---------------- problem constants -------------------------------------------
#define BB 8
#define CC 64
#define HC 32
#define NN 4096
#define LOG2E 1.4426950408889634f

// ---------------- device scratch -----------------------------------------------
__device__ __align__(16) float g_xq[BB * CC * NN];            // [b][c][n]
__device__ __align__(16) unsigned short g_qhi[BB * NN * HC];  // bf16(q*log2e) hi
__device__ __align__(16) unsigned short g_qlo[BB * NN * HC];  // residual
__device__ __align__(16) unsigned short g_khi[BB * NN * HC];
__device__ __align__(16) unsigned short g_klo[BB * NN * HC];
__device__ __align__(16) unsigned short g_vthi[BB * HC * NN]; // bf16 V^T [b][d][n]
__device__ __align__(16) unsigned short g_vtlo[BB * HC * NN];

// ---------------- kernel B: weight quant + x fake-quant + fused QKV -------------
__global__ void __launch_bounds__(128) k_xq_qkv(const float* __restrict__ x,
                                                const float* __restrict__ wq,
                                                const float* __restrict__ wk,
                                                const float* __restrict__ wv,
                                                const float* __restrict__ bq,
                                                const float* __restrict__ bk,
                                                const float* __restrict__ bv,
                                                const float* __restrict__ s_in_p) {
    extern __shared__ float smB[];
    float* xs = smB;                 // [64][128]
    float* ws = smB + CC * 128;      // [64][96]
    __shared__ float redw[12];
    const int t = threadIdx.x;
    const int b = blockIdx.y;
    const int n0 = blockIdx.x * 128;
    const float si = s_in_p[0];

    // ---- x fake-quant into smem + global ----
    const float* xb = x + ((size_t)b * CC) * NN + n0;
    float* xqb = g_xq + ((size_t)b * CC) * NN + n0;
#pragma unroll 4
    for (int c = 0; c < CC; c++) {
        float v = xb[c * NN + t];
        float r = rintf(v / si);
        r = fminf(fmaxf(r, -128.f), 127.f);
        float q = r * si;
        xqb[c * NN + t] = q;
        xs[c * 128 + t] = q;
    }

    // ---- per-tensor weight max-abs (redundant per block; deterministic) ----
    float mx0 = 0.f, mx1 = 0.f, mx2 = 0.f;
    for (int i = t; i < CC * HC; i += 128) {
        mx0 = fmaxf(mx0, fabsf(wq[i]));
        mx1 = fmaxf(mx1, fabsf(wk[i]));
        mx2 = fmaxf(mx2, fabsf(wv[i]));
    }
#pragma unroll
    for (int s = 16; s; s >>= 1) {
        mx0 = fmaxf(mx0, __shfl_xor_sync(0xffffffffu, mx0, s));
        mx1 = fmaxf(mx1, __shfl_xor_sync(0xffffffffu, mx1, s));
        mx2 = fmaxf(mx2, __shfl_xor_sync(0xffffffffu, mx2, s));
    }
    if ((t & 31) == 0) {
        redw[t >> 5] = mx0; redw[4 + (t >> 5)] = mx1; redw[8 + (t >> 5)] = mx2;
    }
    __syncthreads();
    float s0 = fmaxf(fmaxf(redw[0], redw[1]), fmaxf(redw[2], redw[3])) / 127.f;
    float s1 = fmaxf(fmaxf(redw[4], redw[5]), fmaxf(redw[6], redw[7])) / 127.f;
    float s2 = fmaxf(fmaxf(redw[8], redw[9]), fmaxf(redw[10], redw[11])) / 127.f;
    // quantize weights into transposed smem [c][96]
    for (int i = t; i < CC * HC; i += 128) {
        int hc = i >> 6, c = i & 63;
        ws[c * 96 + hc]      = fminf(fmaxf(rintf(wq[i] / s0), -127.f), 127.f) * s0;
        ws[c * 96 + 32 + hc] = fminf(fmaxf(rintf(wk[i] / s1), -127.f), 127.f) * s1;
        ws[c * 96 + 64 + hc] = fminf(fmaxf(rintf(wv[i] / s2), -127.f), 127.f) * s2;
    }
    __syncthreads();

    ull aq[16], ak[16], av[16];
#pragma unroll
    for (int h = 0; h < 16; h++) {
        aq[h] = pack2(bq[2 * h], bq[2 * h + 1]);
        ak[h] = pack2(bk[2 * h], bk[2 * h + 1]);
        av[h] = pack2(bv[2 * h], bv[2 * h + 1]);
    }
#pragma unroll 2
    for (int c = 0; c < CC; c++) {
        float xv = xs[c * 128 + t];
        ull xp = pack2(xv, xv);
        const ulonglong2* wr = (const ulonglong2*)(ws + c * 96);
#pragma unroll
        for (int j = 0; j < 8; j++) {
            ulonglong2 u = wr[j];
            fma2(aq[2 * j], xp, u.x);
            fma2(aq[2 * j + 1], xp, u.y);
        }
#pragma unroll
        for (int j = 0; j < 8; j++) {
            ulonglong2 u = wr[8 + j];
            fma2(ak[2 * j], xp, u.x);
            fma2(ak[2 * j + 1], xp, u.y);
        }
#pragma unroll
        for (int j = 0; j < 8; j++) {
            ulonglong2 u = wr[16 + j];
            fma2(av[2 * j], xp, u.x);
            fma2(av[2 * j + 1], xp, u.y);
        }
    }

    size_t bn = (size_t)b * NN + n0 + t;
    // Q scaled by log2e (exp -> single ex2 later); symmetric hi/lo for Q and K.
    uint32_t qh[16], ql[16], kh[16], kl[16];
#pragma unroll
    for (int j = 0; j < 16; j++) {
        float f0, f1;
        unpack2(aq[j], f0, f1);
        f0 *= LOG2E; f1 *= LOG2E;
        uint32_t u = packbf(f0, f1);
        qh[j] = u;
        ql[j] = packbf(f0 - loF(u), f1 - hiF(u));
        unpack2(ak[j], f0, f1);
        u = packbf(f0, f1);
        kh[j] = u;
        kl[j] = packbf(f0 - loF(u), f1 - hiF(u));
    }
    uint4* qhp = (uint4*)(g_qhi + bn * HC);
    uint4* qlp = (uint4*)(g_qlo + bn * HC);
    uint4* khp = (uint4*)(g_khi + bn * HC);
    uint4* klp = (uint4*)(g_klo + bn * HC);
#pragma unroll
    for (int c4 = 0; c4 < 4; c4++) {
        uint4 u;
        u.x = qh[4 * c4]; u.y = qh[4 * c4 + 1]; u.z = qh[4 * c4 + 2]; u.w = qh[4 * c4 + 3];
        qhp[c4] = u;
        u.x = ql[4 * c4]; u.y = ql[4 * c4 + 1]; u.z = ql[4 * c4 + 2]; u.w = ql[4 * c4 + 3];
        qlp[c4] = u;
        u.x = kh[4 * c4]; u.y = kh[4 * c4 + 1]; u.z = kh[4 * c4 + 2]; u.w = kh[4 * c4 + 3];
        khp[c4] = u;
        u.x = kl[4 * c4]; u.y = kl[4 * c4 + 1]; u.z = kl[4 * c4 + 2]; u.w = kl[4 * c4 + 3];
        klp[c4] = u;
    }
    unsigned short* vh = g_vthi + (size_t)b * HC * NN + n0 + t;
    unsigned short* vl = g_vtlo + (size_t)b * HC * NN + n0 + t;
#pragma unroll
    for (int j = 0; j < 16; j++) {
        float f0, f1;
        unpack2(av[j], f0, f1);
        uint32_t u = packbf(f0, f1);
        uint32_t r = packbf(f0 - loF(u), f1 - hiF(u));
        vh[(size_t)(2 * j) * NN] = (unsigned short)(u & 0xffffu);
        vh[(size_t)(2 * j + 1) * NN] = (unsigned short)(u >> 16);
        vl[(size_t)(2 * j) * NN] = (unsigned short)(r & 0xffffu);
        vl[(size_t)(2 * j + 1) * NN] = (unsigned short)(r >> 16);
    }
}

// ---------------- kernel C: HMMA flash attention + fused proj ---------------------
// grid (16, 8) = (q-tile 256, batch), 256 threads / 8 warps, 32 q-rows per warp.
// R7 structure + latency fixes: ldmatrix.x4 (half the LDSM chains), depth-1
// K-fragment prefetch in the S loop, V fragments hoisted above exp/pack, raw ex2.
#define SM_QHI 0            // 256 rows x 80B
#define SM_QLO 20480
#define SM_K   40960        // + buf*10240 : KHI 64x80, KLO at +5120
#define SM_V   61440        // + buf*9216  : VHI 32x144, VLO at +4608
#define SM_Z   40960        // epilogue reuse: 256 x 34 f32
#define SM_WP  79872        // wp quantized 64x32 f32
#define SM_BP  88064        // bp 64 f32
#define ATTN_SMEM 88320

__global__ void __launch_bounds__(256, 1) k_attn(const float* __restrict__ wp,
                                                 const float* __restrict__ bp,
                                                 const float* __restrict__ s_in_p,
                                                 const float* __restrict__ s_out_p,
                                                 float* __restrict__ out) {
    extern __shared__ char sm[];
    __shared__ float redp[8];
    uint32_t sb = cvta_s(sm);
    const int t = threadIdx.x;
    const int w = t >> 5, lane = t & 31;
    const int b = blockIdx.y, qt = blockIdx.x;
    const int q0 = w * 32;

    const char* pkhi = (const char*)g_khi + (size_t)b * NN * 64;
    const char* pklo = (const char*)g_klo + (size_t)b * NN * 64;
    const char* pvhi = (const char*)g_vthi + (size_t)b * HC * (NN * 2);
    const char* pvlo = (const char*)g_vtlo + (size_t)b * HC * (NN * 2);

    auto stageKV = [&](int kt) {
        uint32_t kb = sb + SM_K + (kt & 1) * 10240;
        uint32_t vb = sb + SM_V + (kt & 1) * 9216;
#pragma unroll
        for (int i = 0; i < 4; i++) {
            int idx = t + i * 256;
            if (idx < 512) {
                int part = idx >> 8, rem = idx & 255;
                int row = rem >> 2, ch = rem & 3;
                const char* src = (part ? pklo : pkhi) + (size_t)(kt * 64 + row) * 64 + ch * 16;
                cpa16(kb + part * 5120 + row * 80 + ch * 16, src);
            } else {
                int part = (idx >> 8) - 2, rem = idx & 255;
                int d = rem >> 3, ch = rem & 7;
                const char* src = (part ? pvlo : pvhi) + (size_t)d * (NN * 2) + kt * 128 + ch * 16;
                cpa16(vb + part * 4608 + d * 144 + ch * 16, src);
            }
        }
    };

    // ---- prologue: stage Q + KV(0); quantize wp while cp.async flies ----
    {
        const char* pqhi = (const char*)g_qhi + (size_t)b * NN * 64;
        const char* pqlo = (const char*)g_qlo + (size_t)b * NN * 64;
#pragma unroll
        for (int i = 0; i < 8; i++) {
            int idx = t + i * 256;
            int part = idx >> 10, rem = idx & 1023;
            int row = rem >> 2, ch = rem & 3;
            const char* src = (part ? pqlo : pqhi) + (size_t)(qt * 256 + row) * 64 + ch * 16;
            cpa16(sb + SM_QHI + part * 20480 + row * 80 + ch * 16, src);
        }
    }
    stageKV(0);
    CP_COMMIT();
    {
        float mxp = 0.f;
        for (int i = t; i < CC * HC; i += 256) mxp = fmaxf(mxp, fabsf(wp[i]));
#pragma unroll
        for (int s = 16; s; s >>= 1) mxp = fmaxf(mxp, __shfl_xor_sync(0xffffffffu, mxp, s));
        if (lane == 0) redp[w] = mxp;
        __syncthreads();
        float sp = fmaxf(fmaxf(fmaxf(redp[0], redp[1]), fmaxf(redp[2], redp[3])),
                         fmaxf(fmaxf(redp[4], redp[5]), fmaxf(redp[6], redp[7]))) / 127.f;
        float* wsp = (float*)(sm + SM_WP);
        for (int i = t; i < CC * HC; i += 256)
            wsp[i] = fminf(fmaxf(rintf(wp[i] / sp), -127.f), 127.f) * sp;
        if (t < CC) ((float*)(sm + SM_BP))[t] = bp[t];
    }
    CP_WAIT0();
    __syncthreads();

    // Q fragments (2 m-tiles x 2 k16 chunks, hi + lo) via ldmatrix.x4
    uint32_t qfh[2][2][4], qfl[2][2][4];
#pragma unroll
    for (int m = 0; m < 2; m++) {
        uint32_t qa = sb + SM_QHI +
            (uint32_t)((q0 + m * 16 + (lane & 7) + ((lane >> 3) & 1) * 8) * 80 +
                       ((lane >> 4) & 1) * 16);
        ldmx4(qfh[m][0], qa);
        ldmx4(qfh[m][1], qa + 32);
        ldmx4(qfl[m][0], qa + 20480);
        ldmx4(qfl[m][1], qa + 20480 + 32);
    }

    float O[2][4][4];
    float l_acc[2][2] = {{0.f, 0.f}, {0.f, 0.f}};
#pragma unroll
    for (int m = 0; m < 2; m++)
#pragma unroll
        for (int n = 0; n < 4; n++)
#pragma unroll
            for (int i = 0; i < 4; i++) O[m][n][i] = 0.f;

    // ---- main loop: 64 tiles of 64 keys ----
    for (int kt = 0; kt < 64; kt++) {
        uint32_t kb = sb + SM_K + (kt & 1) * 10240;
        uint32_t vb = sb + SM_V + (kt & 1) * 9216;
        if (kt < 63) { stageKV(kt + 1); CP_COMMIT(); }

        // K x4 fragment address: keys j*8+(lane&7), dim chunk (lane>>3)*16 bytes.
        // r0,r1 = ks0 (b0,b1); r2,r3 = ks1 (b0,b1).
        const uint32_t ka0 = kb + (uint32_t)((lane & 7) * 80 + (lane >> 3) * 16);

        // S = Q K^T (hi*hi + lo*hi + hi*lo) with depth-1 K-fragment prefetch
        float S[2][8][4];
#pragma unroll
        for (int m = 0; m < 2; m++)
#pragma unroll
            for (int j = 0; j < 8; j++)
#pragma unroll
                for (int i = 0; i < 4; i++) S[m][j][i] = 0.f;

        uint32_t kfh[2][4], kfl[2][4];
        ldmx4(kfh[0], ka0);
        ldmx4(kfl[0], ka0 + 5120);
#pragma unroll
        for (int j = 0; j < 8; j++) {
            const int cur = j & 1, nxt = cur ^ 1;
            if (j < 7) {
                ldmx4(kfh[nxt], ka0 + (uint32_t)((j + 1) * 8 * 80));
                ldmx4(kfl[nxt], ka0 + (uint32_t)((j + 1) * 8 * 80) + 5120);
            }
            // ks = 0 (dims 0-15)
            mma16816(S[0][j], qfh[0][0], kfh[cur][0], kfh[cur][1]);
            mma16816(S[0][j], qfl[0][0], kfh[cur][0], kfh[cur][1]);
            mma16816(S[0][j], qfh[0][0], kfl[cur][0], kfl[cur][1]);
            mma16816(S[1][j], qfh[1][0], kfh[cur][0], kfh[cur][1]);
            mma16816(S[1][j], qfl[1][0], kfh[cur][0], kfh[cur][1]);
            mma16816(S[1][j], qfh[1][0], kfl[cur][0], kfl[cur][1]);
            // ks = 1 (dims 16-31)
            mma16816(S[0][j], qfh[0][1], kfh[cur][2], kfh[cur][3]);
            mma16816(S[0][j], qfl[0][1], kfh[cur][2], kfh[cur][3]);
            mma16816(S[0][j], qfh[0][1], kfl[cur][2], kfl[cur][3]);
            mma16816(S[1][j], qfh[1][1], kfh[cur][2], kfh[cur][3]);
            mma16816(S[1][j], qfl[1][1], kfh[cur][2], kfh[cur][3]);
            mma16816(S[1][j], qfh[1][1], kfl[cur][2], kfl[cur][3]);
        }

        // V x4 fragment base: d rows (lane&15 pattern), key chunk from lane groups.
        // For n-pair p: r0,r1 = (n=2p; kc0,kc1), r2,r3 = (n=2p+1; kc0,kc1).
        const uint32_t va0 = vb +
            (uint32_t)((((lane >> 4) & 1) * 8 + (lane & 7)) * 144 + ((lane >> 3) & 1) * 16);

        // PV in 16-key chunks: V loads hoisted above exp/pack (ALU covers LDS latency)
#pragma unroll
        for (int kk = 0; kk < 4; kk++) {
            uint32_t vfh[8], vfl[8];
            ldmx4(vfh, va0 + kk * 32);                       // n 0-1
            ldmx4(vfh + 4, va0 + kk * 32 + 16 * 144);        // n 2-3
            ldmx4(vfl, va0 + 4608 + kk * 32);
            ldmx4(vfl + 4, va0 + 4608 + kk * 32 + 16 * 144);

            uint32_t phi[2][4], plo[2][4];
#pragma unroll
            for (int m = 0; m < 2; m++) {
                const int j0 = 2 * kk, j1 = 2 * kk + 1;
                float e0 = ex2f(S[m][j0][0]);
                float e1 = ex2f(S[m][j0][1]);
                float e2 = ex2f(S[m][j0][2]);
                float e3 = ex2f(S[m][j0][3]);
                float e4 = ex2f(S[m][j1][0]);
                float e5 = ex2f(S[m][j1][1]);
                float e6 = ex2f(S[m][j1][2]);
                float e7 = ex2f(S[m][j1][3]);
                l_acc[m][0] += (e0 + e1) + (e4 + e5);
                l_acc[m][1] += (e2 + e3) + (e6 + e7);
                uint32_t u;
                u = packbf(e0, e1); phi[m][0] = u;
                plo[m][0] = packbf(e0 - loF(u), e1 - hiF(u));
                u = packbf(e2, e3); phi[m][1] = u;
                plo[m][1] = packbf(e2 - loF(u), e3 - hiF(u));
                u = packbf(e4, e5); phi[m][2] = u;
                plo[m][2] = packbf(e4 - loF(u), e5 - hiF(u));
                u = packbf(e6, e7); phi[m][3] = u;
                plo[m][3] = packbf(e6 - loF(u), e7 - hiF(u));
            }
#pragma unroll
            for (int n = 0; n < 4; n++) {
                uint32_t b0 = vfh[2 * n], b1 = vfh[2 * n + 1];
                uint32_t c0 = vfl[2 * n], c1 = vfl[2 * n + 1];
                mma16816(O[0][n], phi[0], b0, b1);
                mma16816(O[0][n], plo[0], b0, b1);
                mma16816(O[0][n], phi[0], c0, c1);
                mma16816(O[1][n], phi[1], b0, b1);
                mma16816(O[1][n], plo[1], b0, b1);
                mma16816(O[1][n], phi[1], c0, c1);
            }
        }

        if (kt < 63) CP_WAIT0();
        __syncthreads();
    }

    // ---- epilogue 1: l-reduce, normalize, fake-quant z, stage to smem ----
    const float si = s_in_p[0];
    const float so = s_out_p[0];
    float* zs = (float*)(sm + SM_Z);
#pragma unroll
    for (int m = 0; m < 2; m++)
#pragma unroll
        for (int h = 0; h < 2; h++) {
            float lv = l_acc[m][h];
            lv += __shfl_xor_sync(0xffffffffu, lv, 1);
            lv += __shfl_xor_sync(0xffffffffu, lv, 2);
            float inv = 1.0f / lv;
            int row = q0 + m * 16 + (lane >> 2) + h * 8;
#pragma unroll
            for (int n = 0; n < 4; n++) {
                float z0 = O[m][n][h * 2 + 0] * inv;
                float z1 = O[m][n][h * 2 + 1] * inv;
                float r0 = fminf(fmaxf(rintf(z0 / si), -128.f), 127.f) * si;
                float r1 = fminf(fmaxf(rintf(z1 / si), -128.f), 127.f) * si;
                float2 u; u.x = r0; u.y = r1;
                *(float2*)(zs + row * 34 + n * 8 + (lane & 3) * 2) = u;
            }
        }
    __syncthreads();

    // ---- epilogue 2: output projection + residual + out fq (thread = pixel) ----
    {
        ull zp[16];
#pragma unroll
        for (int j = 0; j < 16; j++)
            zp[j] = pack2(zs[t * 34 + 2 * j], zs[t * 34 + 2 * j + 1]);
        const float* wsp = (const float*)(sm + SM_WP);
        const float* bps = (const float*)(sm + SM_BP);
        const float* xqb = g_xq + ((size_t)b * CC) * NN + qt * 256 + t;
        float* ob = out + ((size_t)b * CC) * NN + qt * 256 + t;
#pragma unroll
        for (int c0 = 0; c0 < CC; c0 += 16) {
            float xv[16];
#pragma unroll
            for (int u = 0; u < 16; u++) xv[u] = xqb[(size_t)(c0 + u) * NN];
#pragma unroll
            for (int u = 0; u < 16; u++) {
                int c = c0 + u;
                ull a0 = 0ull, a1 = 0ull;
                const ulonglong2* wr = (const ulonglong2*)(wsp + c * HC);
#pragma unroll
                for (int j = 0; j < 8; j++) {
                    ulonglong2 uu = wr[j];
                    fma2(a0, zp[2 * j], uu.x);
                    fma2(a1, zp[2 * j + 1], uu.y);
                }
                float f0, f1, f2, f3;
                unpack2(a0, f0, f1);
                unpack2(a1, f2, f3);
                float val = xv[u] + (f0 + f1) + (f2 + f3) + bps[c];
                float r = rintf(val / so);
                r = fminf(fmaxf(r, -128.f), 127.f);
                ob[(size_t)c * NN] = r * so;
            }
        }
    }
}

// ---------------- launch ----------------------------------------------------------
extern "C" void kernel_launch(void* const* d_in, const int* in_sizes, int n_in,
                              void* d_out, int out_size) {
    const float* x     = (const float*)d_in[0];
    const float* wq    = (const float*)d_in[1];
    const float* bq    = (const float*)d_in[2];
    const float* wk    = (const float*)d_in[3];
    const float* bk    = (const float*)d_in[4];
    const float* wv    = (const float*)d_in[5];
    const float* bv    = (const float*)d_in[6];
    const float* wp    = (const float*)d_in[7];
    const float* bp    = (const float*)d_in[8];
    const float* s_in  = (const float*)d_in[9];
    const float* s_out = (const float*)d_in[10];
    float* out = (float*)d_out;

    const int smemB = (CC * 128 + CC * 96) * 4;
    cudaFuncSetAttribute(k_xq_qkv, cudaFuncAttributeMaxDynamicSharedMemorySize, smemB);
    cudaFuncSetAttribute(k_attn, cudaFuncAttributeMaxDynamicSharedMemorySize, ATTN_SMEM);

    k_xq_qkv<<<dim3(32, 8), 128, smemB>>>(x, wq, wk, wv, bq, bk, bv, s_in);
    k_attn<<<dim3(16, 8), 256, ATTN_SMEM>>>(wp, bp, s_in, s_out, out);
}